// round 4
// baseline (speedup 1.0000x reference)
#include <cuda_runtime.h>
#include <cuda_bf16.h>
#include <cstdint>

// Problem constants
#define DN   128      // embedding dim
#define CN   50       // conv channels
#define RNUM 237      // relations
#define BNUM 16384    // triples
#define TPC  16       // triples per CTA
#define KCH  24       // chunks per relation (capacity 384 triples/relation)

// ---- device scratch (no allocations allowed) ----
__device__ int g_count[RNUM];
__device__ int g_start[RNUM];
__device__ int g_cursor[RNUM];
__device__ int g_sorted[BNUM];

// ---------------------------------------------------------------------------
// Prep kernels: bucket triples by relation (hist -> scan -> scatter)
// ---------------------------------------------------------------------------
__global__ void k_zero() {
    int i = threadIdx.x;
    if (i < RNUM) g_count[i] = 0;
}

__global__ void k_hist(const int* __restrict__ triples) {
    __shared__ int sh[RNUM];
    for (int i = threadIdx.x; i < RNUM; i += blockDim.x) sh[i] = 0;
    __syncthreads();
    int i = blockIdx.x * blockDim.x + threadIdx.x;
    if (i < BNUM) atomicAdd(&sh[triples[3 * i + 1]], 1);
    __syncthreads();
    for (int i2 = threadIdx.x; i2 < RNUM; i2 += blockDim.x) {
        int v = sh[i2];
        if (v) atomicAdd(&g_count[i2], v);
    }
}

__global__ void k_scan() {
    // 32 threads: lane l handles bins [8l, 8l+8)
    int l = threadIdx.x;
    int vals[8];
    int sum = 0;
#pragma unroll
    for (int j = 0; j < 8; j++) {
        int b = l * 8 + j;
        vals[j] = sum;
        sum += (b < RNUM) ? g_count[b] : 0;
    }
    int x = sum;
#pragma unroll
    for (int sft = 1; sft < 32; sft <<= 1) {
        int y = __shfl_up_sync(0xffffffffu, x, sft);
        if (l >= sft) x += y;
    }
    int off = x - sum;  // exclusive prefix of lane sums
#pragma unroll
    for (int j = 0; j < 8; j++) {
        int b = l * 8 + j;
        if (b < RNUM) {
            int s = off + vals[j];
            g_start[b]  = s;
            g_cursor[b] = s;
        }
    }
}

__global__ void k_scatter(const int* __restrict__ triples) {
    int i = blockIdx.x * blockDim.x + threadIdx.x;
    if (i < BNUM) {
        int r = triples[3 * i + 1];
        int pos = atomicAdd(&g_cursor[r], 1);
        g_sorted[pos] = i;
    }
}

// ---------------------------------------------------------------------------
// Main kernel: one CTA = (relation r, chunk of up to 16 triples)
//   smem: Wr[128][128] (64KB), X[16][2][128] (16KB), rel[128], fc_w (25.6KB),
//         conv_w/conv_b, triple ids
//   4 warps; warp w owns triples 4w..4w+3; lane l owns output cols 4l..4l+3
// ---------------------------------------------------------------------------
#define SMEM_FLOATS (DN*DN + TPC*2*DN + DN + CN*DN + 152 + 56)
#define SMEM_BYTES  (SMEM_FLOATS*4 + TPC*4)

__global__ __launch_bounds__(128)
void k_main(const int* __restrict__ triples,
            const float* __restrict__ ent_emb,
            const float* __restrict__ rel_emb,
            const float* __restrict__ rel_W,
            const float* __restrict__ conv_w,
            const float* __restrict__ conv_b,
            const float* __restrict__ fc_w,
            const float* __restrict__ fc_b,
            float* __restrict__ out)
{
    const int r     = blockIdx.x / KCH;
    const int chunk = blockIdx.x % KCH;

    const int cnt  = g_count[r];
    const int base = chunk * TPC;
    const int n    = min(TPC, cnt - base);
    if (n <= 0) return;
    const int gbase = g_start[r] + base;

    extern __shared__ float smem[];
    float* sWr  = smem;                       // 16384 floats
    float* sX   = sWr + DN * DN;              // 4096 floats : [slot][h(128)|t(128)]
    float* sRel = sX + TPC * 2 * DN;          // 128
    float* sFcw = sRel + DN;                  // 6400
    float* sCw  = sFcw + CN * DN;             // 150 (+pad 2)
    float* sCb  = sCw + 152;                  // 50 (+pad 6)
    int*   sTid = (int*)(sCb + 56);           // 16 ints

    const int tid = threadIdx.x;

    // ---- stage Wr (64KB) ----
    {
        const float4* gW = (const float4*)(rel_W + (size_t)r * DN * DN);
        float4* sW4 = (float4*)sWr;
#pragma unroll 4
        for (int i = tid; i < DN * DN / 4; i += 128) sW4[i] = gW[i];
    }
    // ---- stage fc_w ----
    {
        const float4* gF = (const float4*)fc_w;
        float4* sF4 = (float4*)sFcw;
        for (int i = tid; i < CN * DN / 4; i += 128) sF4[i] = gF[i];
    }
    // ---- stage rel_emb[r], conv_w, conv_b ----
    if (tid < 32) ((float4*)sRel)[tid] = ((const float4*)(rel_emb + (size_t)r * DN))[tid];
    for (int i = tid; i < CN * 3; i += 128) sCw[i] = conv_w[i];
    if (tid < CN) sCb[tid] = conv_b[tid];

    // ---- stage entity rows: 8 threads per slot ----
    {
        const int s = tid >> 3;        // 0..15
        const int l8 = tid & 7;
        float4* sX4 = (float4*)sX;
        if (s < n) {
            int i = g_sorted[gbase + s];
            if (l8 == 0) sTid[s] = i;
            int h = triples[3 * i + 0];
            int t = triples[3 * i + 2];
            const float4* eh = (const float4*)(ent_emb + (size_t)h * DN);
            const float4* et = (const float4*)(ent_emb + (size_t)t * DN);
#pragma unroll
            for (int kk = 0; kk < 4; kk++) {
                sX4[s * 64 + kk * 8 + l8]      = eh[kk * 8 + l8];
                sX4[s * 64 + 32 + kk * 8 + l8] = et[kk * 8 + l8];
            }
        } else {
            float4 z = make_float4(0.f, 0.f, 0.f, 0.f);
#pragma unroll
            for (int kk = 0; kk < 4; kk++) {
                sX4[s * 64 + kk * 8 + l8]      = z;
                sX4[s * 64 + 32 + kk * 8 + l8] = z;
            }
        }
    }
    __syncthreads();

    // ---- register-blocked matvecs: warp w -> triples 4w..4w+3, lane l -> cols 4l..4l+3
    const int l  = tid & 31;
    const int w  = tid >> 5;
    const int tb = w * 4;

    float acc[4][8];   // [triple][0..3 = ph cols, 4..7 = pt cols]
#pragma unroll
    for (int q = 0; q < 4; q++)
#pragma unroll
        for (int j = 0; j < 8; j++) acc[q][j] = 0.f;

    const float4* sW4  = (const float4*)sWr;
    const float4* sX4c = (const float4*)sX;

#pragma unroll 2
    for (int d4 = 0; d4 < DN / 4; d4++) {
        float4 wr[4];
#pragma unroll
        for (int dd = 0; dd < 4; dd++) wr[dd] = sW4[(d4 * 4 + dd) * 32 + l];
#pragma unroll
        for (int q = 0; q < 4; q++) {
            float4 xh = sX4c[(tb + q) * 64 + d4];
            float4 xt = sX4c[(tb + q) * 64 + 32 + d4];
            const float* xhp = &xh.x;
            const float* xtp = &xt.x;
#pragma unroll
            for (int dd = 0; dd < 4; dd++) {
                const float* wp = &wr[dd].x;
#pragma unroll
                for (int j = 0; j < 4; j++) {
                    acc[q][j]     = fmaf(xhp[dd], wp[j], acc[q][j]);
                    acc[q][4 + j] = fmaf(xtp[dd], wp[j], acc[q][4 + j]);
                }
            }
        }
    }

    // ---- conv + relu + fc epilogue ----
    float4 rr = ((const float4*)sRel)[l];
    const float* rrp = &rr.x;
    float part[4] = {0.f, 0.f, 0.f, 0.f};
    const float4* sF4 = (const float4*)sFcw;

#pragma unroll 2
    for (int c = 0; c < CN; c++) {
        float cw0 = sCw[3 * c + 0];
        float cw1 = sCw[3 * c + 1];
        float cw2 = sCw[3 * c + 2];
        float cb  = sCb[c];
        float4 fw = sF4[c * 32 + l];
        const float* fwp = &fw.x;
#pragma unroll
        for (int q = 0; q < 4; q++) {
#pragma unroll
            for (int j = 0; j < 4; j++) {
                float f = fmaf(acc[q][j], cw0,
                          fmaf(rrp[j],   cw1,
                          fmaf(acc[q][4 + j], cw2, cb)));
                f = fmaxf(f, 0.f);
                part[q] = fmaf(f, fwp[j], part[q]);
            }
        }
    }

    const float fcb = __ldg(fc_b);
#pragma unroll
    for (int q = 0; q < 4; q++) {
        float v = part[q];
#pragma unroll
        for (int s = 16; s; s >>= 1) v += __shfl_xor_sync(0xffffffffu, v, s);
        if (l == 0 && tb + q < n) out[sTid[tb + q]] = v + fcb;
    }
}

// ---------------------------------------------------------------------------
extern "C" void kernel_launch(void* const* d_in, const int* in_sizes, int n_in,
                              void* d_out, int out_size)
{
    const int*   triples = (const int*)d_in[0];
    const float* ent_emb = (const float*)d_in[1];
    const float* rel_emb = (const float*)d_in[2];
    const float* rel_W   = (const float*)d_in[3];
    const float* conv_w  = (const float*)d_in[4];
    const float* conv_b  = (const float*)d_in[5];
    const float* fc_w    = (const float*)d_in[6];
    const float* fc_b    = (const float*)d_in[7];
    float* out = (float*)d_out;

    // idempotent; not a stream op, safe under graph capture
    cudaFuncSetAttribute(k_main, cudaFuncAttributeMaxDynamicSharedMemorySize, SMEM_BYTES);

    k_zero<<<1, 256>>>();
    k_hist<<<(BNUM + 255) / 256, 256>>>(triples);
    k_scan<<<1, 32>>>();
    k_scatter<<<(BNUM + 255) / 256, 256>>>(triples);
    k_main<<<RNUM * KCH, 128, SMEM_BYTES>>>(triples, ent_emb, rel_emb, rel_W,
                                            conv_w, conv_b, fc_w, fc_b, out);
}